// round 15
// baseline (speedup 1.0000x reference)
#include <cuda_runtime.h>
#include <cuda_fp16.h>
#include <cstdint>

#define BATCH 8192
#define HID   512
#define HID2  1024
#define NSTEPS 10
#define NEVAL  (NSTEPS*4)
#define ITEMS_PER_EVAL 1280          // 512 G1 + 512 G2 + 256 G3
#define TOTAL_ITEMS (NEVAL*ITEMS_PER_EVAL)
#define NSYNC (NEVAL*3*64 + 1)       // counters + ticket

// ---------------- scratch (device globals; no allocation anywhere) -----------
__device__ __half g_x1[(size_t)BATCH * HID2];
__device__ __half g_x2[(size_t)BATCH * HID2];
__device__ float  g_acc[(size_t)BATCH * HID];
__device__ __half g_htmp[(size_t)BATCH * HID];
__device__ float  g_h[(size_t)BATCH * HID];
__device__ __half g_hr[(size_t)BATCH * HID];
__device__ __half g_w1[(size_t)HID2 * HID];
__device__ __half g_w2[(size_t)HID2 * HID2];
__device__ __half g_w3[(size_t)HID  * HID2];
__device__ float  g_c1[NEVAL * HID2];
__device__ int    g_sync[NSYNC];

// ---------------- helpers ----------------------------------------------------
__device__ __forceinline__ void mma16(float* d, const unsigned* a, const unsigned* b) {
    asm volatile(
        "mma.sync.aligned.m16n8k16.row.col.f32.f16.f16.f32 "
        "{%0,%1,%2,%3}, {%4,%5,%6,%7}, {%8,%9}, {%0,%1,%2,%3};\n"
        : "+f"(d[0]), "+f"(d[1]), "+f"(d[2]), "+f"(d[3])
        : "r"(a[0]), "r"(a[1]), "r"(a[2]), "r"(a[3]), "r"(b[0]), "r"(b[1]));
}

__device__ __forceinline__ float tanh_fast(float x) {
    float y;
    asm("tanh.approx.f32 %0, %1;" : "=f"(y) : "f"(x));
    return y;
}

#define LDSM4(r, a) \
    asm volatile("ldmatrix.sync.aligned.m8n8.x4.shared.b16 {%0,%1,%2,%3}, [%4];" \
                 : "=r"((r)[0]), "=r"((r)[1]), "=r"((r)[2]), "=r"((r)[3]) : "r"(a))

// ---------------- prep kernels -----------------------------------------------
__global__ void half2_kernel(const float2* __restrict__ src, __half2* __restrict__ dst, int n2) {
    int i = blockIdx.x * blockDim.x + threadIdx.x;
    if (i < n2) {
        float2 v = src[i];
        dst[i] = __floats2half2_rn(v.x, v.y);
    }
}

// c1[e][j] = b1[j] + sum_i W1[j,i]*(t_e*Wt[i]+bt[i]); also zeroes sync counters
__global__ void c1_all_kernel(const float* __restrict__ W1, const float* __restrict__ b1,
                              const float* __restrict__ Wt, const float* __restrict__ bt,
                              float dt, float* __restrict__ out, int* __restrict__ syncp) {
    int gi = blockIdx.x * blockDim.x + threadIdx.x;
    if (gi < NSYNC) syncp[gi] = 0;
    int gw = gi >> 5;
    int lane = threadIdx.x & 31;
    int e = gw >> 10;
    int j = gw & 1023;
    if (e >= NEVAL) return;
    int step = e >> 2, st = e & 3;
    float tv = step * dt + ((st == 0) ? 0.0f : (st == 3) ? dt : 0.5f * dt);
    const float* row = W1 + (size_t)j * HID;
    float s = 0.0f;
    #pragma unroll 4
    for (int i = lane; i < HID; i += 32)
        s = fmaf(row[i], fmaf(tv, Wt[i], bt[i]), s);
    #pragma unroll
    for (int o = 16; o; o >>= 1) s += __shfl_xor_sync(0xffffffffu, s, o);
    if (lane == 0) out[e * HID2 + j] = b1[j] + s;
}

// ---------------- persistent dataflow kernel ---------------------------------
// One launch runs all 40 evals x 3 GEMMs as 51200 tile-items pulled from a
// global ticket, with per-(eval,128-rowblock) dependency counters.
// Mainloop = proven R12/R13 ldmatrix fp16 body. Epilogue: tanh.approx +
// vectorized (__half2 / float2) memory.
__global__ __launch_bounds__(256, 2)
void ode_persistent(__half* x1, __half* x2, __half* htmp, __half* hr,
                    const __half* w1, const __half* w2, const __half* w3,
                    const float* c1, const float* b2, const float* b3,
                    float* hbuf, float* accbuf, int* syncbuf, float dt) {
    extern __shared__ __half smem[];
    const int STG_B = 128 * 80;               // bytes per stage per matrix
    __half* As = smem;
    __half* Bs = smem + 3 * (STG_B / 2);
    __shared__ int s_item;

    const int t = threadIdx.x;
    const int warp = t >> 5, lane = t & 31;
    const int wm = warp & 1, wn = warp >> 1;  // 2 x 4 warp grid, warp tile 64x32
    const int g = lane >> 2, q = lane & 3;
    const int row0 = t >> 2;
    const int seg  = t & 3;

    const unsigned smemA0 = (unsigned)__cvta_generic_to_shared(As);
    const unsigned smemB0 = (unsigned)__cvta_generic_to_shared(Bs);
    const unsigned sA0 = smemA0 + row0 * 80 + seg * 16;
    const unsigned sB0 = smemB0 + row0 * 80 + seg * 16;
    const unsigned aL0 = smemA0 + (unsigned)(wm * 64 + (lane & 15)) * 80
                       + ((lane >> 4) & 1) * 16;
    const unsigned bL0 = smemB0 + (unsigned)(wn * 32 + ((lane >> 4) & 1) * 8 + (lane & 7)) * 80
                       + ((lane >> 3) & 1) * 16;
    int* ticket = syncbuf + NEVAL * 3 * 64;

    for (;;) {
        if (t == 0) s_item = atomicAdd(ticket, 1);
        __syncthreads();
        const int item = s_item;
        if (item >= TOTAL_ITEMS) break;

        const int e  = item / ITEMS_PER_EVAL;
        const int r  = item - e * ITEMS_PER_EVAL;
        const int st = e & 3;

        const __half *A, *Bw;
        const float* bias;
        __half* C;
        int N, K, bm, bn, stage, depneed = 0;
        const int* dep = nullptr;
        int* sig;
        if (r < 512) {                       // GEMM1
            bm = r >> 3; bn = r & 7;
            A = (st == 0) ? hr : htmp; Bw = w1; bias = c1 + e * HID2; C = x1;
            N = HID2; K = HID; stage = -1;
            if (e > 0) { dep = syncbuf + ((e - 1) * 3 + 2) * 64 + bm; depneed = 4; }
            sig = syncbuf + (e * 3 + 0) * 64 + bm;
        } else if (r < 1024) {               // GEMM2
            int r2 = r - 512; bm = r2 >> 3; bn = r2 & 7;
            A = x1; Bw = w2; bias = b2; C = x2;
            N = HID2; K = HID2; stage = -1;
            dep = syncbuf + (e * 3 + 0) * 64 + bm; depneed = 8;
            sig = syncbuf + (e * 3 + 1) * 64 + bm;
        } else {                             // GEMM3 (+ fused RK4 epilogue)
            int r3 = r - 1024; bm = r3 >> 2; bn = r3 & 3;
            A = x2; Bw = w3; bias = b3; C = nullptr;
            N = HID; K = HID2; stage = st;
            dep = syncbuf + (e * 3 + 1) * 64 + bm; depneed = 8;
            sig = syncbuf + (e * 3 + 2) * 64 + bm;
        }
        const int bmo = bm << 7, bno = bn << 7;
        const __half* Bg = Bw + (size_t)(bno + row0) * K + seg * 8;

        #define LOAD_A(kt, s)                                                          \
        {                                                                              \
            const __half* ap = Ag + (kt) * 32;                                         \
            unsigned sa = sA0 + (unsigned)(s) * STG_B;                                 \
            _Pragma("unroll")                                                          \
            for (int i = 0; i < 2; i++)                                                \
                asm volatile("cp.async.cg.shared.global [%0], [%1], 16;\n"             \
                             :: "r"(sa + i * 64 * 80), "l"(ap + (size_t)i * 64 * K));  \
        }
        #define LOAD_B(kt, s)                                                          \
        {                                                                              \
            const __half* bp = Bg + (kt) * 32;                                         \
            unsigned sb = sB0 + (unsigned)(s) * STG_B;                                 \
            _Pragma("unroll")                                                          \
            for (int i = 0; i < 2; i++)                                                \
                asm volatile("cp.async.cg.shared.global [%0], [%1], 16;\n"             \
                             :: "r"(sb + i * 64 * 80), "l"(bp + (size_t)i * 64 * K));  \
        }
        #define COMMIT() asm volatile("cp.async.commit_group;\n")

        // weights first (dep-free), then spin on producer counters, then A
        LOAD_B(0, 0);
        LOAD_B(1, 1);
        COMMIT();
        if (t == 0 && depneed) {
            while (*(volatile const int*)dep < depneed) __nanosleep(200);
            __threadfence();
        }
        __syncthreads();
        const __half* Ag = A + (size_t)(bmo + row0) * K + seg * 8;
        LOAD_A(0, 0);
        COMMIT();
        LOAD_A(1, 1);
        COMMIT();

        float acc[4][4][4];
        #pragma unroll
        for (int i = 0; i < 4; i++)
            #pragma unroll
            for (int j = 0; j < 4; j++)
                #pragma unroll
                for (int v = 0; v < 4; v++) acc[i][j][v] = 0.0f;

        const int KT = K >> 5;
        for (int kt = 0; kt < KT; kt++) {
            if (kt + 1 == KT) asm volatile("cp.async.wait_group 0;\n");
            else              asm volatile("cp.async.wait_group 1;\n");
            __syncthreads();
            const int cur = kt % 3;
            const unsigned aS = aL0 + (unsigned)cur * STG_B;
            const unsigned bS = bL0 + (unsigned)cur * STG_B;
            #pragma unroll
            for (int s = 0; s < 2; s++) {
                unsigned bfr[8];
                LDSM4(&bfr[0], bS + s * 32);
                LDSM4(&bfr[4], bS + s * 32 + 16 * 80);
                #pragma unroll
                for (int fm = 0; fm < 4; fm++) {
                    unsigned af[4];
                    LDSM4(af, aS + s * 32 + (unsigned)(fm * 16) * 80);
                    #pragma unroll
                    for (int fn = 0; fn < 4; fn++)
                        mma16(acc[fm][fn], af, &bfr[fn * 2]);
                }
            }
            if (kt + 2 < KT) {
                const int nxt = (kt + 2) % 3;
                LOAD_A(kt + 2, nxt);
                LOAD_B(kt + 2, nxt);
                COMMIT();
            }
        }
        #undef LOAD_A
        #undef LOAD_B
        #undef COMMIT

        // ---------------- epilogue (vectorized) ----------------
        #pragma unroll
        for (int fm = 0; fm < 4; fm++) {
            int r0 = bmo + wm * 64 + fm * 16 + g;
            int r1 = r0 + 8;
            #pragma unroll
            for (int fn = 0; fn < 4; fn++) {
                int c = bno + wn * 32 + fn * 8 + 2 * q;
                float bc0 = bias[c], bc1 = bias[c + 1];
                float v0 = acc[fm][fn][0] + bc0;   // (r0, c)
                float v1 = acc[fm][fn][1] + bc1;   // (r0, c+1)
                float v2 = acc[fm][fn][2] + bc0;   // (r1, c)
                float v3 = acc[fm][fn][3] + bc1;   // (r1, c+1)
                const size_t i0 = (size_t)r0 * N + c;
                const size_t i1 = (size_t)r1 * N + c;
                if (stage < 0) {
                    *(__half2*)(C + i0) = __floats2half2_rn(tanh_fast(v0), tanh_fast(v1));
                    *(__half2*)(C + i1) = __floats2half2_rn(tanh_fast(v2), tanh_fast(v3));
                } else if (stage == 0) {
                    float2 h0 = *(const float2*)(hbuf + i0);
                    float2 h1 = *(const float2*)(hbuf + i1);
                    *(float2*)(accbuf + i0) = make_float2(v0, v1);
                    *(float2*)(accbuf + i1) = make_float2(v2, v3);
                    *(__half2*)(htmp + i0) = __floats2half2_rn(h0.x + 0.5f * dt * v0,
                                                               h0.y + 0.5f * dt * v1);
                    *(__half2*)(htmp + i1) = __floats2half2_rn(h1.x + 0.5f * dt * v2,
                                                               h1.y + 0.5f * dt * v3);
                } else if (stage == 1 || stage == 2) {
                    const float co = (stage == 2) ? dt : 0.5f * dt;
                    float2 h0 = *(const float2*)(hbuf + i0);
                    float2 h1 = *(const float2*)(hbuf + i1);
                    float2 a0 = *(const float2*)(accbuf + i0);
                    float2 a1 = *(const float2*)(accbuf + i1);
                    a0.x += 2.0f * v0; a0.y += 2.0f * v1;
                    a1.x += 2.0f * v2; a1.y += 2.0f * v3;
                    *(float2*)(accbuf + i0) = a0;
                    *(float2*)(accbuf + i1) = a1;
                    *(__half2*)(htmp + i0) = __floats2half2_rn(h0.x + co * v0, h0.y + co * v1);
                    *(__half2*)(htmp + i1) = __floats2half2_rn(h1.x + co * v2, h1.y + co * v3);
                } else {
                    float2 h0 = *(const float2*)(hbuf + i0);
                    float2 h1 = *(const float2*)(hbuf + i1);
                    float2 a0 = *(const float2*)(accbuf + i0);
                    float2 a1 = *(const float2*)(accbuf + i1);
                    float n0 = h0.x + (dt / 6.0f) * (a0.x + v0);
                    float n1 = h0.y + (dt / 6.0f) * (a0.y + v1);
                    float n2 = h1.x + (dt / 6.0f) * (a1.x + v2);
                    float n3 = h1.y + (dt / 6.0f) * (a1.y + v3);
                    *(float2*)(hbuf + i0) = make_float2(n0, n1);
                    *(float2*)(hbuf + i1) = make_float2(n2, n3);
                    *(__half2*)(hr + i0) = __floats2half2_rn(n0, n1);
                    *(__half2*)(hr + i1) = __floats2half2_rn(n2, n3);
                }
            }
        }

        __threadfence();
        __syncthreads();
        if (t == 0) atomicAdd(sig, 1);
    }
}

// ---------------- launch -----------------------------------------------------
extern "C" void kernel_launch(void* const* d_in, const int* in_sizes, int n_in,
                              void* d_out, int out_size) {
    const float* h  = (const float*)d_in[0];
    const float* W1 = (const float*)d_in[1];
    const float* b1 = (const float*)d_in[2];
    const float* W2 = (const float*)d_in[3];
    const float* b2 = (const float*)d_in[4];
    const float* W3 = (const float*)d_in[5];
    const float* b3 = (const float*)d_in[6];
    const float* Wt = (const float*)d_in[7];
    const float* bt = (const float*)d_in[8];
    (void)in_sizes; (void)n_in; (void)out_size;

    __half *x1, *x2, *htmp, *hr, *w1, *w2, *w3;
    float *accb, *hbuf, *c1;
    int* syncbuf;
    cudaGetSymbolAddress((void**)&x1,      g_x1);
    cudaGetSymbolAddress((void**)&x2,      g_x2);
    cudaGetSymbolAddress((void**)&accb,    g_acc);
    cudaGetSymbolAddress((void**)&htmp,    g_htmp);
    cudaGetSymbolAddress((void**)&hbuf,    g_h);
    cudaGetSymbolAddress((void**)&hr,      g_hr);
    cudaGetSymbolAddress((void**)&w1,      g_w1);
    cudaGetSymbolAddress((void**)&w2,      g_w2);
    cudaGetSymbolAddress((void**)&w3,      g_w3);
    cudaGetSymbolAddress((void**)&c1,      g_c1);
    cudaGetSymbolAddress((void**)&syncbuf, g_sync);

    const int SMEM = 6 * 128 * 80;      // 61440 B (3 stages x (A+B))
    cudaFuncSetAttribute(ode_persistent, cudaFuncAttributeMaxDynamicSharedMemorySize, SMEM);

    cudaMemcpyAsync(hbuf, h, (size_t)BATCH * HID * sizeof(float), cudaMemcpyDeviceToDevice);

    const float dt = 1.0f / NSTEPS;

    // prep (exactly 5 kernel launches so ncu -s 5 captures ode_persistent):
    // fp16-round weights and h, c1 vectors + sync-counter zeroing
    {
        int n2;
        n2 = HID2 * HID / 2;   half2_kernel<<<(n2 + 255) / 256, 256>>>((const float2*)W1, (__half2*)w1, n2);
        n2 = HID2 * HID2 / 2;  half2_kernel<<<(n2 + 255) / 256, 256>>>((const float2*)W2, (__half2*)w2, n2);
        n2 = HID * HID2 / 2;   half2_kernel<<<(n2 + 255) / 256, 256>>>((const float2*)W3, (__half2*)w3, n2);
        n2 = BATCH * HID / 2;  half2_kernel<<<(n2 + 255) / 256, 256>>>((const float2*)h,  (__half2*)hr, n2);
        c1_all_kernel<<<NEVAL * HID2 / 8, 256>>>(W1, b1, Wt, bt, dt, c1, syncbuf);
    }

    // one persistent kernel runs the whole 40-eval chain
    ode_persistent<<<296, 256, SMEM>>>(x1, x2, htmp, hr, w1, w2, w3,
                                       c1, b2, b3, hbuf, accb, syncbuf, dt);

    cudaMemcpyAsync(d_out, hbuf, (size_t)BATCH * HID * sizeof(float), cudaMemcpyDeviceToDevice);
}

// round 16
// speedup vs baseline: 1.2450x; 1.2450x over previous
#include <cuda_runtime.h>
#include <cuda_fp16.h>
#include <cstdint>

#define BATCH 8192
#define HID   512
#define HID2  1024
#define NSTEPS 10
#define NEVAL  (NSTEPS*4)
#define ITEMS_PER_EVAL 1280          // 512 G1 + 512 G2 + 256 G3
#define TOTAL_ITEMS (NEVAL*ITEMS_PER_EVAL)
#define NSYNC (NEVAL*3*64 + 1)       // counters + ticket

// ---------------- scratch (device globals; no allocation anywhere) -----------
__device__ __half g_x1[(size_t)BATCH * HID2];
__device__ __half g_x2[(size_t)BATCH * HID2];
__device__ float  g_acc[(size_t)BATCH * HID];
__device__ __half g_htmp[(size_t)BATCH * HID];
__device__ float  g_h[(size_t)BATCH * HID];
__device__ __half g_hr[(size_t)BATCH * HID];
__device__ __half g_w1[(size_t)HID2 * HID];
__device__ __half g_w2[(size_t)HID2 * HID2];
__device__ __half g_w3[(size_t)HID  * HID2];
__device__ float  g_c1[NEVAL * HID2];
__device__ int    g_sync[NSYNC];

// ---------------- helpers ----------------------------------------------------
__device__ __forceinline__ void mma16(float* d, const unsigned* a, const unsigned* b) {
    asm volatile(
        "mma.sync.aligned.m16n8k16.row.col.f32.f16.f16.f32 "
        "{%0,%1,%2,%3}, {%4,%5,%6,%7}, {%8,%9}, {%0,%1,%2,%3};\n"
        : "+f"(d[0]), "+f"(d[1]), "+f"(d[2]), "+f"(d[3])
        : "r"(a[0]), "r"(a[1]), "r"(a[2]), "r"(a[3]), "r"(b[0]), "r"(b[1]));
}

__device__ __forceinline__ float tanh_fast(float x) {
    float y;
    asm("tanh.approx.f32 %0, %1;" : "=f"(y) : "f"(x));
    return y;
}

#define LDSM4(r, a) \
    asm volatile("ldmatrix.sync.aligned.m8n8.x4.shared.b16 {%0,%1,%2,%3}, [%4];" \
                 : "=r"((r)[0]), "=r"((r)[1]), "=r"((r)[2]), "=r"((r)[3]) : "r"(a))

// ---------------- prep kernels -----------------------------------------------
__global__ void half2_kernel(const float2* __restrict__ src, __half2* __restrict__ dst, int n2) {
    int i = blockIdx.x * blockDim.x + threadIdx.x;
    if (i < n2) {
        float2 v = src[i];
        dst[i] = __floats2half2_rn(v.x, v.y);
    }
}

__global__ void zero_sync_kernel(int* p, int n) {
    int i = blockIdx.x * blockDim.x + threadIdx.x;
    if (i < n) p[i] = 0;
}

// c1[e][j] = b1[j] + sum_i W1[j,i]*(t_e*Wt[i]+bt[i])
__global__ void c1_all_kernel(const float* __restrict__ W1, const float* __restrict__ b1,
                              const float* __restrict__ Wt, const float* __restrict__ bt,
                              float dt, float* __restrict__ out) {
    int gw = (blockIdx.x * blockDim.x + threadIdx.x) >> 5;
    int lane = threadIdx.x & 31;
    int e = gw >> 10;
    int j = gw & 1023;
    if (e >= NEVAL) return;
    int step = e >> 2, st = e & 3;
    float tv = step * dt + ((st == 0) ? 0.0f : (st == 3) ? dt : 0.5f * dt);
    const float* row = W1 + (size_t)j * HID;
    float s = 0.0f;
    #pragma unroll 4
    for (int i = lane; i < HID; i += 32)
        s = fmaf(row[i], fmaf(tv, Wt[i], bt[i]), s);
    #pragma unroll
    for (int o = 16; o; o >>= 1) s += __shfl_xor_sync(0xffffffffu, s, o);
    if (lane == 0) out[e * HID2 + j] = b1[j] + s;
}

// ---------------- persistent dataflow kernel ---------------------------------
// One launch runs all 40 evals x 3 GEMMs as 51200 tile-items pulled from a
// global ticket, with per-(eval,128-rowblock) dependency counters.
// Tile body = proven R12/R13 ldmatrix fp16 kernel. Single change from R13:
// tanhf -> tanh.approx.f32 (fewer instructions, fewer live temporaries).
__global__ __launch_bounds__(256, 2)
void ode_persistent(__half* x1, __half* x2, __half* htmp, __half* hr,
                    const __half* w1, const __half* w2, const __half* w3,
                    const float* c1, const float* b2, const float* b3,
                    float* hbuf, float* accbuf, int* syncbuf, float dt) {
    extern __shared__ __half smem[];
    const int STG_B = 128 * 80;               // bytes per stage per matrix
    __half* As = smem;
    __half* Bs = smem + 3 * (STG_B / 2);
    __shared__ int s_item;

    const int t = threadIdx.x;
    const int warp = t >> 5, lane = t & 31;
    const int wm = warp & 1, wn = warp >> 1;  // 2 x 4 warp grid, warp tile 64x32
    const int g = lane >> 2, q = lane & 3;
    const int row0 = t >> 2;
    const int seg  = t & 3;

    const unsigned smemA0 = (unsigned)__cvta_generic_to_shared(As);
    const unsigned smemB0 = (unsigned)__cvta_generic_to_shared(Bs);
    const unsigned sA0 = smemA0 + row0 * 80 + seg * 16;
    const unsigned sB0 = smemB0 + row0 * 80 + seg * 16;
    const unsigned aL0 = smemA0 + (unsigned)(wm * 64 + (lane & 15)) * 80
                       + ((lane >> 4) & 1) * 16;
    const unsigned bL0 = smemB0 + (unsigned)(wn * 32 + ((lane >> 4) & 1) * 8 + (lane & 7)) * 80
                       + ((lane >> 3) & 1) * 16;
    int* ticket = syncbuf + NEVAL * 3 * 64;

    for (;;) {
        if (t == 0) s_item = atomicAdd(ticket, 1);
        __syncthreads();
        const int item = s_item;
        if (item >= TOTAL_ITEMS) break;

        const int e  = item / ITEMS_PER_EVAL;
        const int r  = item - e * ITEMS_PER_EVAL;
        const int st = e & 3;

        const __half *A, *Bw;
        const float* bias;
        __half* C;
        int N, K, bm, bn, stage, depneed = 0;
        const int* dep = nullptr;
        int* sig;
        if (r < 512) {                       // GEMM1
            bm = r >> 3; bn = r & 7;
            A = (st == 0) ? hr : htmp; Bw = w1; bias = c1 + e * HID2; C = x1;
            N = HID2; K = HID; stage = -1;
            if (e > 0) { dep = syncbuf + ((e - 1) * 3 + 2) * 64 + bm; depneed = 4; }
            sig = syncbuf + (e * 3 + 0) * 64 + bm;
        } else if (r < 1024) {               // GEMM2
            int r2 = r - 512; bm = r2 >> 3; bn = r2 & 7;
            A = x1; Bw = w2; bias = b2; C = x2;
            N = HID2; K = HID2; stage = -1;
            dep = syncbuf + (e * 3 + 0) * 64 + bm; depneed = 8;
            sig = syncbuf + (e * 3 + 1) * 64 + bm;
        } else {                             // GEMM3 (+ fused RK4 epilogue)
            int r3 = r - 1024; bm = r3 >> 2; bn = r3 & 3;
            A = x2; Bw = w3; bias = b3; C = nullptr;
            N = HID; K = HID2; stage = st;
            dep = syncbuf + (e * 3 + 1) * 64 + bm; depneed = 8;
            sig = syncbuf + (e * 3 + 2) * 64 + bm;
        }
        const int bmo = bm << 7, bno = bn << 7;
        const __half* Bg = Bw + (size_t)(bno + row0) * K + seg * 8;

        #define LOAD_A(kt, s)                                                          \
        {                                                                              \
            const __half* ap = Ag + (kt) * 32;                                         \
            unsigned sa = sA0 + (unsigned)(s) * STG_B;                                 \
            _Pragma("unroll")                                                          \
            for (int i = 0; i < 2; i++)                                                \
                asm volatile("cp.async.cg.shared.global [%0], [%1], 16;\n"             \
                             :: "r"(sa + i * 64 * 80), "l"(ap + (size_t)i * 64 * K));  \
        }
        #define LOAD_B(kt, s)                                                          \
        {                                                                              \
            const __half* bp = Bg + (kt) * 32;                                         \
            unsigned sb = sB0 + (unsigned)(s) * STG_B;                                 \
            _Pragma("unroll")                                                          \
            for (int i = 0; i < 2; i++)                                                \
                asm volatile("cp.async.cg.shared.global [%0], [%1], 16;\n"             \
                             :: "r"(sb + i * 64 * 80), "l"(bp + (size_t)i * 64 * K));  \
        }
        #define COMMIT() asm volatile("cp.async.commit_group;\n")

        // weights first (dep-free), then spin on producer counters, then A
        LOAD_B(0, 0);
        LOAD_B(1, 1);
        COMMIT();
        if (t == 0 && depneed) {
            while (*(volatile const int*)dep < depneed) __nanosleep(200);
            __threadfence();
        }
        __syncthreads();
        const __half* Ag = A + (size_t)(bmo + row0) * K + seg * 8;
        LOAD_A(0, 0);
        COMMIT();
        LOAD_A(1, 1);
        COMMIT();

        float acc[4][4][4];
        #pragma unroll
        for (int i = 0; i < 4; i++)
            #pragma unroll
            for (int j = 0; j < 4; j++)
                #pragma unroll
                for (int v = 0; v < 4; v++) acc[i][j][v] = 0.0f;

        const int KT = K >> 5;
        for (int kt = 0; kt < KT; kt++) {
            if (kt + 1 == KT) asm volatile("cp.async.wait_group 0;\n");
            else              asm volatile("cp.async.wait_group 1;\n");
            __syncthreads();
            const int cur = kt % 3;
            const unsigned aS = aL0 + (unsigned)cur * STG_B;
            const unsigned bS = bL0 + (unsigned)cur * STG_B;
            #pragma unroll
            for (int s = 0; s < 2; s++) {
                unsigned bfr[8];
                LDSM4(&bfr[0], bS + s * 32);
                LDSM4(&bfr[4], bS + s * 32 + 16 * 80);
                #pragma unroll
                for (int fm = 0; fm < 4; fm++) {
                    unsigned af[4];
                    LDSM4(af, aS + s * 32 + (unsigned)(fm * 16) * 80);
                    #pragma unroll
                    for (int fn = 0; fn < 4; fn++)
                        mma16(acc[fm][fn], af, &bfr[fn * 2]);
                }
            }
            if (kt + 2 < KT) {
                const int nxt = (kt + 2) % 3;
                LOAD_A(kt + 2, nxt);
                LOAD_B(kt + 2, nxt);
                COMMIT();
            }
        }
        #undef LOAD_A
        #undef LOAD_B
        #undef COMMIT

        // epilogue (R13 scalar form; only tanh changed to approx)
        #pragma unroll
        for (int fm = 0; fm < 4; fm++) {
            int r0 = bmo + wm * 64 + fm * 16 + g;
            int r1 = r0 + 8;
            #pragma unroll
            for (int fn = 0; fn < 4; fn++) {
                int c = bno + wn * 32 + fn * 8 + 2 * q;
                float bc0 = bias[c], bc1 = bias[c + 1];
                float v[4];
                v[0] = acc[fm][fn][0] + bc0;
                v[1] = acc[fm][fn][1] + bc1;
                v[2] = acc[fm][fn][2] + bc0;
                v[3] = acc[fm][fn][3] + bc1;
                int idx[4] = { r0 * N + c, r0 * N + c + 1, r1 * N + c, r1 * N + c + 1 };
                if (stage < 0) {
                    #pragma unroll
                    for (int u = 0; u < 4; u++)
                        C[idx[u]] = __float2half_rn(tanh_fast(v[u]));
                } else if (stage == 0) {
                    #pragma unroll
                    for (int u = 0; u < 4; u++) {
                        accbuf[idx[u]] = v[u];
                        htmp[idx[u]]   = __float2half_rn(hbuf[idx[u]] + 0.5f * dt * v[u]);
                    }
                } else if (stage == 1) {
                    #pragma unroll
                    for (int u = 0; u < 4; u++) {
                        accbuf[idx[u]] += 2.0f * v[u];
                        htmp[idx[u]]    = __float2half_rn(hbuf[idx[u]] + 0.5f * dt * v[u]);
                    }
                } else if (stage == 2) {
                    #pragma unroll
                    for (int u = 0; u < 4; u++) {
                        accbuf[idx[u]] += 2.0f * v[u];
                        htmp[idx[u]]    = __float2half_rn(hbuf[idx[u]] + dt * v[u]);
                    }
                } else {
                    #pragma unroll
                    for (int u = 0; u < 4; u++) {
                        float hn = hbuf[idx[u]] + (dt / 6.0f) * (accbuf[idx[u]] + v[u]);
                        hbuf[idx[u]] = hn;
                        hr[idx[u]]   = __float2half_rn(hn);
                    }
                }
            }
        }

        __threadfence();
        __syncthreads();
        if (t == 0) atomicAdd(sig, 1);
    }
}

// ---------------- launch -----------------------------------------------------
extern "C" void kernel_launch(void* const* d_in, const int* in_sizes, int n_in,
                              void* d_out, int out_size) {
    const float* h  = (const float*)d_in[0];
    const float* W1 = (const float*)d_in[1];
    const float* b1 = (const float*)d_in[2];
    const float* W2 = (const float*)d_in[3];
    const float* b2 = (const float*)d_in[4];
    const float* W3 = (const float*)d_in[5];
    const float* b3 = (const float*)d_in[6];
    const float* Wt = (const float*)d_in[7];
    const float* bt = (const float*)d_in[8];
    (void)in_sizes; (void)n_in; (void)out_size;

    __half *x1, *x2, *htmp, *hr, *w1, *w2, *w3;
    float *accb, *hbuf, *c1;
    int* syncbuf;
    cudaGetSymbolAddress((void**)&x1,      g_x1);
    cudaGetSymbolAddress((void**)&x2,      g_x2);
    cudaGetSymbolAddress((void**)&accb,    g_acc);
    cudaGetSymbolAddress((void**)&htmp,    g_htmp);
    cudaGetSymbolAddress((void**)&hbuf,    g_h);
    cudaGetSymbolAddress((void**)&hr,      g_hr);
    cudaGetSymbolAddress((void**)&w1,      g_w1);
    cudaGetSymbolAddress((void**)&w2,      g_w2);
    cudaGetSymbolAddress((void**)&w3,      g_w3);
    cudaGetSymbolAddress((void**)&c1,      g_c1);
    cudaGetSymbolAddress((void**)&syncbuf, g_sync);

    const int SMEM = 6 * 128 * 80;      // 61440 B (3 stages x (A+B))
    cudaFuncSetAttribute(ode_persistent, cudaFuncAttributeMaxDynamicSharedMemorySize, SMEM);

    cudaMemcpyAsync(hbuf, h, (size_t)BATCH * HID * sizeof(float), cudaMemcpyDeviceToDevice);

    const float dt = 1.0f / NSTEPS;

    // prep: fp16-round weights and h, c1 vectors, zero sync counters
    {
        int n2;
        n2 = HID2 * HID / 2;   half2_kernel<<<(n2 + 255) / 256, 256>>>((const float2*)W1, (__half2*)w1, n2);
        n2 = HID2 * HID2 / 2;  half2_kernel<<<(n2 + 255) / 256, 256>>>((const float2*)W2, (__half2*)w2, n2);
        n2 = HID * HID2 / 2;   half2_kernel<<<(n2 + 255) / 256, 256>>>((const float2*)W3, (__half2*)w3, n2);
        n2 = BATCH * HID / 2;  half2_kernel<<<(n2 + 255) / 256, 256>>>((const float2*)h,  (__half2*)hr, n2);
        c1_all_kernel<<<NEVAL * HID2 / 8, 256>>>(W1, b1, Wt, bt, dt, c1);
        zero_sync_kernel<<<(NSYNC + 255) / 256, 256>>>(syncbuf, NSYNC);
    }

    // one persistent kernel runs the whole 40-eval chain
    ode_persistent<<<296, 256, SMEM>>>(x1, x2, htmp, hr, w1, w2, w3,
                                       c1, b2, b3, hbuf, accb, syncbuf, dt);

    cudaMemcpyAsync(d_out, hbuf, (size_t)BATCH * HID * sizeof(float), cudaMemcpyDeviceToDevice);
}

// round 17
// speedup vs baseline: 1.2857x; 1.0327x over previous
#include <cuda_runtime.h>
#include <cuda_fp16.h>
#include <cstdint>

#define BATCH 8192
#define HID   512
#define HID2  1024
#define NSTEPS 10
#define NEVAL  (NSTEPS*4)
#define ITEMS_PER_EVAL 1280          // 512 G1 + 512 G2 + 256 G3
#define TOTAL_ITEMS (NEVAL*ITEMS_PER_EVAL)
#define NSYNC (NEVAL*3*64 + 1)       // counters + ticket

// ---------------- scratch (device globals; no allocation anywhere) -----------
__device__ __half g_x1[(size_t)BATCH * HID2];
__device__ __half g_x2[(size_t)BATCH * HID2];
__device__ float  g_acc[(size_t)BATCH * HID];
__device__ __half g_htmp[(size_t)BATCH * HID];
__device__ float  g_h[(size_t)BATCH * HID];
__device__ __half g_hr[(size_t)BATCH * HID];
__device__ __half g_w1[(size_t)HID2 * HID];
__device__ __half g_w2[(size_t)HID2 * HID2];
__device__ __half g_w3[(size_t)HID  * HID2];
__device__ float  g_c1[NEVAL * HID2];
__device__ int    g_sync[NSYNC];

// ---------------- helpers ----------------------------------------------------
__device__ __forceinline__ void mma16(float* d, const unsigned* a, const unsigned* b) {
    asm volatile(
        "mma.sync.aligned.m16n8k16.row.col.f32.f16.f16.f32 "
        "{%0,%1,%2,%3}, {%4,%5,%6,%7}, {%8,%9}, {%0,%1,%2,%3};\n"
        : "+f"(d[0]), "+f"(d[1]), "+f"(d[2]), "+f"(d[3])
        : "r"(a[0]), "r"(a[1]), "r"(a[2]), "r"(a[3]), "r"(b[0]), "r"(b[1]));
}

__device__ __forceinline__ float tanh_fast(float x) {
    float y;
    asm("tanh.approx.f32 %0, %1;" : "=f"(y) : "f"(x));
    return y;
}

#define LDSM4(r, a) \
    asm volatile("ldmatrix.sync.aligned.m8n8.x4.shared.b16 {%0,%1,%2,%3}, [%4];" \
                 : "=r"((r)[0]), "=r"((r)[1]), "=r"((r)[2]), "=r"((r)[3]) : "r"(a))

// ---------------- prep kernels -----------------------------------------------
__global__ void half2_kernel(const float2* __restrict__ src, __half2* __restrict__ dst, int n2) {
    int i = blockIdx.x * blockDim.x + threadIdx.x;
    if (i < n2) {
        float2 v = src[i];
        dst[i] = __floats2half2_rn(v.x, v.y);
    }
}

// c1[e][j] = b1[j] + sum_i W1[j,i]*(t_e*Wt[i]+bt[i]); also zeroes sync counters
__global__ void c1_all_kernel(const float* __restrict__ W1, const float* __restrict__ b1,
                              const float* __restrict__ Wt, const float* __restrict__ bt,
                              float dt, float* __restrict__ out, int* __restrict__ syncp) {
    int gi = blockIdx.x * blockDim.x + threadIdx.x;
    if (gi < NSYNC) syncp[gi] = 0;
    int gw = gi >> 5;
    int lane = threadIdx.x & 31;
    int e = gw >> 10;
    int j = gw & 1023;
    if (e >= NEVAL) return;
    int step = e >> 2, st = e & 3;
    float tv = step * dt + ((st == 0) ? 0.0f : (st == 3) ? dt : 0.5f * dt);
    const float* row = W1 + (size_t)j * HID;
    float s = 0.0f;
    #pragma unroll 4
    for (int i = lane; i < HID; i += 32)
        s = fmaf(row[i], fmaf(tv, Wt[i], bt[i]), s);
    #pragma unroll
    for (int o = 16; o; o >>= 1) s += __shfl_xor_sync(0xffffffffu, s, o);
    if (lane == 0) out[e * HID2 + j] = b1[j] + s;
}

// ---------------- persistent dataflow kernel ---------------------------------
// One launch runs all 40 evals x 3 GEMMs as 51200 tile-items pulled from a
// global ticket, with per-(eval,128-rowblock) dependency counters.
// Mainloop: ldmatrix fp16 body with K-chunk = 64 halfs (128 B/row, 144 B
// padded stride) -> half the barriers of the R13 version, identical math.
__global__ __launch_bounds__(256, 2)
void ode_persistent(__half* x1, __half* x2, __half* htmp, __half* hr,
                    const __half* w1, const __half* w2, const __half* w3,
                    const float* c1, const float* b2, const float* b3,
                    float* hbuf, float* accbuf, int* syncbuf, float dt) {
    extern __shared__ __half smem[];
    const int STG_B = 128 * 144;              // bytes per stage per matrix (18432)
    __half* As = smem;
    __half* Bs = smem + 3 * (STG_B / 2);
    __shared__ int s_item;

    const int t = threadIdx.x;
    const int warp = t >> 5, lane = t & 31;
    const int wm = warp & 1, wn = warp >> 1;  // 2 x 4 warp grid, warp tile 64x32
    const int g = lane >> 2, q = lane & 3;
    const int row0 = t >> 3;                  // copy row 0..31 (+32*i)
    const int seg  = t & 7;                   // 16B segment within 128B row

    const unsigned smemA0 = (unsigned)__cvta_generic_to_shared(As);
    const unsigned smemB0 = (unsigned)__cvta_generic_to_shared(Bs);
    const unsigned sA0 = smemA0 + row0 * 144 + seg * 16;
    const unsigned sB0 = smemB0 + row0 * 144 + seg * 16;
    // ldmatrix lane addresses (stage-0, k-step-0 relative)
    const unsigned aL0 = smemA0 + (unsigned)(wm * 64 + (lane & 15)) * 144
                       + ((lane >> 4) & 1) * 16;
    const unsigned bL0 = smemB0 + (unsigned)(wn * 32 + ((lane >> 4) & 1) * 8 + (lane & 7)) * 144
                       + ((lane >> 3) & 1) * 16;
    int* ticket = syncbuf + NEVAL * 3 * 64;

    for (;;) {
        if (t == 0) s_item = atomicAdd(ticket, 1);
        __syncthreads();
        const int item = s_item;
        if (item >= TOTAL_ITEMS) break;

        const int e  = item / ITEMS_PER_EVAL;
        const int r  = item - e * ITEMS_PER_EVAL;
        const int st = e & 3;

        const __half *A, *Bw;
        const float* bias;
        __half* C;
        int N, K, bm, bn, stage, depneed = 0;
        const int* dep = nullptr;
        int* sig;
        if (r < 512) {                       // GEMM1
            bm = r >> 3; bn = r & 7;
            A = (st == 0) ? hr : htmp; Bw = w1; bias = c1 + e * HID2; C = x1;
            N = HID2; K = HID; stage = -1;
            if (e > 0) { dep = syncbuf + ((e - 1) * 3 + 2) * 64 + bm; depneed = 4; }
            sig = syncbuf + (e * 3 + 0) * 64 + bm;
        } else if (r < 1024) {               // GEMM2
            int r2 = r - 512; bm = r2 >> 3; bn = r2 & 7;
            A = x1; Bw = w2; bias = b2; C = x2;
            N = HID2; K = HID2; stage = -1;
            dep = syncbuf + (e * 3 + 0) * 64 + bm; depneed = 8;
            sig = syncbuf + (e * 3 + 1) * 64 + bm;
        } else {                             // GEMM3 (+ fused RK4 epilogue)
            int r3 = r - 1024; bm = r3 >> 2; bn = r3 & 3;
            A = x2; Bw = w3; bias = b3; C = nullptr;
            N = HID; K = HID2; stage = st;
            dep = syncbuf + (e * 3 + 1) * 64 + bm; depneed = 8;
            sig = syncbuf + (e * 3 + 2) * 64 + bm;
        }
        const int bmo = bm << 7, bno = bn << 7;
        const __half* Bg = Bw + (size_t)(bno + row0) * K + seg * 8;

        // one chunk = 64 k-halfs (128 B per row); 4 cp.async per matrix/thread
        #define LOAD_A(kt, s)                                                          \
        {                                                                              \
            const __half* ap = Ag + (kt) * 64;                                         \
            unsigned sa = sA0 + (unsigned)(s) * STG_B;                                 \
            _Pragma("unroll")                                                          \
            for (int i = 0; i < 4; i++)                                                \
                asm volatile("cp.async.cg.shared.global [%0], [%1], 16;\n"             \
                             :: "r"(sa + i * 32 * 144), "l"(ap + (size_t)i * 32 * K)); \
        }
        #define LOAD_B(kt, s)                                                          \
        {                                                                              \
            const __half* bp = Bg + (kt) * 64;                                         \
            unsigned sb = sB0 + (unsigned)(s) * STG_B;                                 \
            _Pragma("unroll")                                                          \
            for (int i = 0; i < 4; i++)                                                \
                asm volatile("cp.async.cg.shared.global [%0], [%1], 16;\n"             \
                             :: "r"(sb + i * 32 * 144), "l"(bp + (size_t)i * 32 * K)); \
        }
        #define COMMIT() asm volatile("cp.async.commit_group;\n")

        // weights first (dep-free), then spin on producer counters, then A
        LOAD_B(0, 0);
        LOAD_B(1, 1);
        COMMIT();
        if (t == 0 && depneed) {
            while (*(volatile const int*)dep < depneed) __nanosleep(200);
            __threadfence();
        }
        __syncthreads();
        const __half* Ag = A + (size_t)(bmo + row0) * K + seg * 8;
        LOAD_A(0, 0);
        COMMIT();
        LOAD_A(1, 1);
        COMMIT();

        float acc[4][4][4];
        #pragma unroll
        for (int i = 0; i < 4; i++)
            #pragma unroll
            for (int j = 0; j < 4; j++)
                #pragma unroll
                for (int v = 0; v < 4; v++) acc[i][j][v] = 0.0f;

        const int KT = K >> 6;               // chunks of 64
        for (int kt = 0; kt < KT; kt++) {
            if (kt + 1 == KT) asm volatile("cp.async.wait_group 0;\n");
            else              asm volatile("cp.async.wait_group 1;\n");
            __syncthreads();
            const int cur = kt % 3;
            const unsigned aS = aL0 + (unsigned)cur * STG_B;
            const unsigned bS = bL0 + (unsigned)cur * STG_B;
            #pragma unroll
            for (int s = 0; s < 4; s++) {    // four k16 steps per 64-chunk
                unsigned bfr[8];
                LDSM4(&bfr[0], bS + s * 32);
                LDSM4(&bfr[4], bS + s * 32 + 16 * 144);
                #pragma unroll
                for (int fm = 0; fm < 4; fm++) {
                    unsigned af[4];
                    LDSM4(af, aS + s * 32 + (unsigned)(fm * 16) * 144);
                    #pragma unroll
                    for (int fn = 0; fn < 4; fn++)
                        mma16(acc[fm][fn], af, &bfr[fn * 2]);
                }
            }
            if (kt + 2 < KT) {
                const int nxt = (kt + 2) % 3;
                LOAD_A(kt + 2, nxt);
                LOAD_B(kt + 2, nxt);
                COMMIT();
            }
        }
        #undef LOAD_A
        #undef LOAD_B
        #undef COMMIT

        // epilogue (proven R13 scalar form, tanh.approx)
        #pragma unroll
        for (int fm = 0; fm < 4; fm++) {
            int r0 = bmo + wm * 64 + fm * 16 + g;
            int r1 = r0 + 8;
            #pragma unroll
            for (int fn = 0; fn < 4; fn++) {
                int c = bno + wn * 32 + fn * 8 + 2 * q;
                float bc0 = bias[c], bc1 = bias[c + 1];
                float v[4];
                v[0] = acc[fm][fn][0] + bc0;
                v[1] = acc[fm][fn][1] + bc1;
                v[2] = acc[fm][fn][2] + bc0;
                v[3] = acc[fm][fn][3] + bc1;
                int idx[4] = { r0 * N + c, r0 * N + c + 1, r1 * N + c, r1 * N + c + 1 };
                if (stage < 0) {
                    #pragma unroll
                    for (int u = 0; u < 4; u++)
                        C[idx[u]] = __float2half_rn(tanh_fast(v[u]));
                } else if (stage == 0) {
                    #pragma unroll
                    for (int u = 0; u < 4; u++) {
                        accbuf[idx[u]] = v[u];
                        htmp[idx[u]]   = __float2half_rn(hbuf[idx[u]] + 0.5f * dt * v[u]);
                    }
                } else if (stage == 1) {
                    #pragma unroll
                    for (int u = 0; u < 4; u++) {
                        accbuf[idx[u]] += 2.0f * v[u];
                        htmp[idx[u]]    = __float2half_rn(hbuf[idx[u]] + 0.5f * dt * v[u]);
                    }
                } else if (stage == 2) {
                    #pragma unroll
                    for (int u = 0; u < 4; u++) {
                        accbuf[idx[u]] += 2.0f * v[u];
                        htmp[idx[u]]    = __float2half_rn(hbuf[idx[u]] + dt * v[u]);
                    }
                } else {
                    #pragma unroll
                    for (int u = 0; u < 4; u++) {
                        float hn = hbuf[idx[u]] + (dt / 6.0f) * (accbuf[idx[u]] + v[u]);
                        hbuf[idx[u]] = hn;
                        hr[idx[u]]   = __float2half_rn(hn);
                    }
                }
            }
        }

        __threadfence();
        __syncthreads();
        if (t == 0) atomicAdd(sig, 1);
    }
}

// ---------------- launch -----------------------------------------------------
extern "C" void kernel_launch(void* const* d_in, const int* in_sizes, int n_in,
                              void* d_out, int out_size) {
    const float* h  = (const float*)d_in[0];
    const float* W1 = (const float*)d_in[1];
    const float* b1 = (const float*)d_in[2];
    const float* W2 = (const float*)d_in[3];
    const float* b2 = (const float*)d_in[4];
    const float* W3 = (const float*)d_in[5];
    const float* b3 = (const float*)d_in[6];
    const float* Wt = (const float*)d_in[7];
    const float* bt = (const float*)d_in[8];
    (void)in_sizes; (void)n_in; (void)out_size;

    __half *x1, *x2, *htmp, *hr, *w1, *w2, *w3;
    float *accb, *hbuf, *c1;
    int* syncbuf;
    cudaGetSymbolAddress((void**)&x1,      g_x1);
    cudaGetSymbolAddress((void**)&x2,      g_x2);
    cudaGetSymbolAddress((void**)&accb,    g_acc);
    cudaGetSymbolAddress((void**)&htmp,    g_htmp);
    cudaGetSymbolAddress((void**)&hbuf,    g_h);
    cudaGetSymbolAddress((void**)&hr,      g_hr);
    cudaGetSymbolAddress((void**)&w1,      g_w1);
    cudaGetSymbolAddress((void**)&w2,      g_w2);
    cudaGetSymbolAddress((void**)&w3,      g_w3);
    cudaGetSymbolAddress((void**)&c1,      g_c1);
    cudaGetSymbolAddress((void**)&syncbuf, g_sync);

    const int SMEM = 6 * 128 * 144;     // 110592 B (3 stages x (A+B), 64-k chunks)
    cudaFuncSetAttribute(ode_persistent, cudaFuncAttributeMaxDynamicSharedMemorySize, SMEM);

    cudaMemcpyAsync(hbuf, h, (size_t)BATCH * HID * sizeof(float), cudaMemcpyDeviceToDevice);

    const float dt = 1.0f / NSTEPS;

    // prep (exactly 5 launches so ncu -s 5 -c 1 captures ode_persistent):
    {
        int n2;
        n2 = HID2 * HID / 2;   half2_kernel<<<(n2 + 255) / 256, 256>>>((const float2*)W1, (__half2*)w1, n2);
        n2 = HID2 * HID2 / 2;  half2_kernel<<<(n2 + 255) / 256, 256>>>((const float2*)W2, (__half2*)w2, n2);
        n2 = HID * HID2 / 2;   half2_kernel<<<(n2 + 255) / 256, 256>>>((const float2*)W3, (__half2*)w3, n2);
        n2 = BATCH * HID / 2;  half2_kernel<<<(n2 + 255) / 256, 256>>>((const float2*)h,  (__half2*)hr, n2);
        c1_all_kernel<<<NEVAL * HID2 / 8, 256>>>(W1, b1, Wt, bt, dt, c1, syncbuf);
    }

    // one persistent kernel runs the whole 40-eval chain
    ode_persistent<<<296, 256, SMEM>>>(x1, x2, htmp, hr, w1, w2, w3,
                                       c1, b2, b3, hbuf, accb, syncbuf, dt);

    cudaMemcpyAsync(d_out, hbuf, (size_t)BATCH * HID * sizeof(float), cudaMemcpyDeviceToDevice);
}